// round 3
// baseline (speedup 1.0000x reference)
#include <cuda_runtime.h>
#include <math.h>

// Problem dims
#define BB 64
#define TT 256
#define ZZ 128
#define HH 512
#define FF 64
#define MROWS (BB*TT)      // 16384
#define G4H   (4*HH)       // 2048
#define LSTM_BLOCKS (HH/4) // 128

// ------------------------------ scratch buffers ------------------------------
__device__ float d_xk[MROWS * G4H];     // 134 MB  gate pre-activations
__device__ float d_seqA[MROWS * HH];
__device__ float d_seqB[MROWS * HH];
__device__ float d_res[MROWS * HH];
__device__ float d_W0eff[ZZ * G4H];
__device__ float d_b0eff[G4H];
__device__ float d_hT[2 * HH * BB];     // double-buffered h, [buf][hidden][batch]
__device__ unsigned g_arrive;
__device__ unsigned g_gen;

__device__ __forceinline__ float sigf(float x) { return 1.f / (1.f + expf(-x)); }

// packed f32x2 helpers (Blackwell)
#define FMA2(c, a, b) \
    asm("fma.rn.f32x2 %0, %2, %3, %1;" : "=l"(c) : "l"(c), "l"(a), "l"(b))
#define ADD2(d, a, b) \
    asm("add.rn.f32x2 %0, %1, %2;" : "=l"(d) : "l"(a), "l"(b))
#define PACKDUP(d, f) \
    asm("mov.b64 %0, {%1, %1};" : "=l"(d) : "r"(__float_as_uint(f)))

__device__ __forceinline__ float f2lo(unsigned long long v) {
    return __uint_as_float((unsigned)v);
}
__device__ __forceinline__ float f2hi(unsigned long long v) {
    return __uint_as_float((unsigned)(v >> 32));
}

// ------------------------------ grid barrier ---------------------------------
__device__ __forceinline__ void grid_barrier() {
    __syncthreads();
    if (threadIdx.x == 0) {
        __threadfence();
        unsigned my = *(volatile unsigned*)&g_gen;
        if (atomicAdd(&g_arrive, 1u) == gridDim.x - 1u) {
            g_arrive = 0u;
            __threadfence();
            atomicAdd(&g_gen, 1u);
        } else {
            while (*(volatile unsigned*)&g_gen == my) {}
        }
        __threadfence();
    }
    __syncthreads();
}

// ------------------------------ bias fold: b0eff = bp@K0 + b0 ----------------
__global__ void bias_fold_kernel(const float* __restrict__ bp,
                                 const float* __restrict__ K0,
                                 const float* __restrict__ b0) {
    __shared__ float red[8][32];
    const int c = threadIdx.x & 31, s = threadIdx.x >> 5;
    const int j = blockIdx.x * 32 + c;
    float acc = 0.f;
    for (int k = s * 128; k < s * 128 + 128; ++k)
        acc += bp[k] * K0[(size_t)k * G4H + j];
    red[s][c] = acc;
    __syncthreads();
    if (s == 0) {
        float t = 0.f;
#pragma unroll
        for (int r = 0; r < 8; ++r) t += red[r][c];
        d_b0eff[j] = t + b0[j];
    }
}

// ------------------------------ SGEMM 128x128x16, 8x8/thread, f32x2 ----------
// AMAP: 0 identity row, 1 (m=(t,b) -> source row b*T+t)
// ACT : 0 none, 1 relu
// ADD2A: A := A + A2 (identity-mapped rows)
// HASB: add bias[n]
template<int AMAP, int ACT, int ADD2A, int HASB>
__global__ __launch_bounds__(256, 2)
void sgemm128(const float* __restrict__ A, const float* __restrict__ A2,
              const float* __restrict__ Bm, const float* __restrict__ bias,
              float* __restrict__ C, int M, int N, int K) {
    __shared__ float As[16][128];
    __shared__ float Bs[16][128];
    const int tid = threadIdx.x;
    const int n0 = blockIdx.x * 128, m0 = blockIdx.y * 128;
    const int r = tid >> 2, kq = (tid & 3) * 4;
    const int kb = tid >> 5, n4 = (tid & 31) * 4;
    const int tm = tid >> 4, tn = tid & 15;

    unsigned long long acc2[8][4];
#pragma unroll
    for (int i = 0; i < 8; ++i)
#pragma unroll
        for (int j = 0; j < 4; ++j) acc2[i][j] = 0ULL;

    for (int k0 = 0; k0 < K; k0 += 16) {
#pragma unroll
        for (int h = 0; h < 2; ++h) {   // A tile, transposed store
            int rr = r + h * 64;
            int m = m0 + rr;
            int arow = (AMAP == 1) ? ((m & 63) * TT + (m >> 6)) : m;
            float4 av = *(const float4*)(A + (size_t)arow * K + k0 + kq);
            if (ADD2A) {
                float4 a2 = *(const float4*)(A2 + (size_t)m * K + k0 + kq);
                av.x += a2.x; av.y += a2.y; av.z += a2.z; av.w += a2.w;
            }
            As[kq + 0][rr] = av.x;
            As[kq + 1][rr] = av.y;
            As[kq + 2][rr] = av.z;
            As[kq + 3][rr] = av.w;
        }
#pragma unroll
        for (int h = 0; h < 2; ++h) {   // B tile
            int kk = kb + h * 8;
            *(float4*)&Bs[kk][n4] =
                *(const float4*)(Bm + (size_t)(k0 + kk) * N + n0 + n4);
        }
        __syncthreads();
#pragma unroll
        for (int k = 0; k < 16; ++k) {
            float4 a0 = *(const float4*)&As[k][tm * 8];
            float4 a1 = *(const float4*)&As[k][tm * 8 + 4];
            const ulonglong2* bp2 = (const ulonglong2*)&Bs[k][tn * 8];
            ulonglong2 bA = bp2[0];
            ulonglong2 bB = bp2[1];
            float ar[8] = {a0.x, a0.y, a0.z, a0.w, a1.x, a1.y, a1.z, a1.w};
#pragma unroll
            for (int i = 0; i < 8; ++i) {
                unsigned long long ad;
                PACKDUP(ad, ar[i]);
                FMA2(acc2[i][0], ad, bA.x);
                FMA2(acc2[i][1], ad, bA.y);
                FMA2(acc2[i][2], ad, bB.x);
                FMA2(acc2[i][3], ad, bB.y);
            }
        }
        __syncthreads();
    }

#pragma unroll
    for (int i = 0; i < 8; ++i) {
        int m = m0 + tm * 8 + i;
        size_t ro = (size_t)m * N;
        float vals[8];
#pragma unroll
        for (int j2 = 0; j2 < 4; ++j2) {
            vals[2 * j2]     = f2lo(acc2[i][j2]);
            vals[2 * j2 + 1] = f2hi(acc2[i][j2]);
        }
#pragma unroll
        for (int j = 0; j < 8; ++j) {
            int n = n0 + tn * 8 + j;
            float t = vals[j];
            if (HASB) t += bias[n];
            if (ACT == 1) t = fmaxf(t, 0.f);
            vals[j] = t;
        }
        float4 v0 = make_float4(vals[0], vals[1], vals[2], vals[3]);
        float4 v1 = make_float4(vals[4], vals[5], vals[6], vals[7]);
        *(float4*)(C + ro + n0 + tn * 8)     = v0;
        *(float4*)(C + ro + n0 + tn * 8 + 4) = v1;
    }
}

// ------------------------------ SGEMM 64x64x16 (small shapes) ----------------
// OMAP: 0 identity, 1 (t,b)->(b,t) output rows ; ACT: 0 none, 2 tanh
template<int ACT, int OMAP, int HASB>
__global__ __launch_bounds__(256)
void sgemm64(const float* __restrict__ A, const float* __restrict__ Bm,
             const float* __restrict__ bias, float* __restrict__ C,
             int M, int N, int K) {
    __shared__ float As[16][64];
    __shared__ float Bs[16][64];
    const int tid = threadIdx.x;
    const int tx = tid & 15, ty = tid >> 4;
    const int n0 = blockIdx.x * 64, m0 = blockIdx.y * 64;

    float acc[4][4];
#pragma unroll
    for (int i = 0; i < 4; ++i)
#pragma unroll
        for (int j = 0; j < 4; ++j) acc[i][j] = 0.f;

    const int arowl = tid >> 2;
    const int kq = (tid & 3) * 4;
    const int krow = tid >> 4;
    const int nq = (tid & 15) * 4;

    for (int k0 = 0; k0 < K; k0 += 16) {
        {
            int m = m0 + arowl;
            float4 av = *(const float4*)(A + (size_t)m * K + k0 + kq);
            As[kq + 0][arowl] = av.x;
            As[kq + 1][arowl] = av.y;
            As[kq + 2][arowl] = av.z;
            As[kq + 3][arowl] = av.w;
        }
        *(float4*)&Bs[krow][nq] =
            *(const float4*)(Bm + (size_t)(k0 + krow) * N + n0 + nq);
        __syncthreads();
#pragma unroll
        for (int k = 0; k < 16; ++k) {
            float4 a = *(const float4*)&As[k][ty * 4];
            float4 b = *(const float4*)&Bs[k][tx * 4];
            float ar[4] = {a.x, a.y, a.z, a.w};
            float br[4] = {b.x, b.y, b.z, b.w};
#pragma unroll
            for (int i = 0; i < 4; ++i)
#pragma unroll
                for (int j = 0; j < 4; ++j) acc[i][j] += ar[i] * br[j];
        }
        __syncthreads();
    }

#pragma unroll
    for (int i = 0; i < 4; ++i) {
        int m = m0 + ty * 4 + i;
        size_t ro = (OMAP == 1) ? (size_t)((m & 63) * TT + (m >> 6)) * N
                                : (size_t)m * N;
        float4 v;
        float* vp = (float*)&v;
#pragma unroll
        for (int j = 0; j < 4; ++j) {
            int n = n0 + tx * 4 + j;
            float t = acc[i][j];
            if (HASB) t += bias[n];
            if (ACT == 2) t = tanhf(t);
            vp[j] = t;
        }
        *(float4*)(C + ro + n0 + tx * 4) = v;
    }
}

// ------------------------------ LSTM recurrence ------------------------------
// 128 blocks x 512 threads. Block owns 4 hidden units (16 gate cols).
// Rs duplicated layout: element (k=s*64+kk, gate cg, unit u) stored TWICE at
// float index 2*pos, 2*pos+1 where pos = kk*128 + cg*32 + s*4 + u.
// -> inner loop: 1 LDG.128(h via L2) + 2 LDS.128 + 8 fma.rn.f32x2 per kk.
__global__ __launch_bounds__(512)
void lstm_kernel(const float* __restrict__ xk, const float* __restrict__ R,
                 float* __restrict__ hseq) {
    __shared__ float Rsd[HH * 16 * 2];  // 64 KB duplicated R slice
    __shared__ float gsm[BB * 16];      // gates
    __shared__ float csm[BB * 4];       // cell state
    __shared__ float xsm[BB * 16];      // staged xk tile

    const int tid = threadIdx.x;
    const int cb = blockIdx.x * 4;

    // load R slice duplicated
    for (int idx = tid; idx < HH * 16; idx += 512) {
        int k = idx >> 4, jl = idx & 15;
        int cg = jl >> 2, u = jl & 3;
        int s = k >> 6, kk = k & 63;
        int pos = (kk << 7) + (cg << 5) + (s << 2) + u;
        float v = R[(size_t)k * G4H + cg * HH + cb + u];
        Rsd[2 * pos]     = v;
        Rsd[2 * pos + 1] = v;
    }
    // zero h buffer 0 (our 4 units) + cell state
    for (int i = tid; i < 4 * BB; i += 512)
        __stcg(&d_hT[(cb + (i >> 6)) * BB + (i & 63)], 0.f);
    if (tid < 256) csm[tid] = 0.f;
    grid_barrier();

    const int lane = tid & 31;
    const int warp = tid >> 5;       // bg: 16 warps x 4 batches
    const int s    = lane & 7;       // k split 8
    const int cg   = lane >> 3;      // gate 0..3
    const int bg   = warp;

    const unsigned long long* Rs64 = (const unsigned long long*)Rsd;

    for (int t = 0; t < TT; ++t) {
        const float* hcur = d_hT + (t & 1) * (HH * BB);
        float* hnxt       = d_hT + ((t + 1) & 1) * (HH * BB);
        const float* xkt  = xk + (size_t)t * BB * G4H;

        // stage xk tile for this step (consumed after the syncthreads below)
        if (tid < 256) {
            int b = tid >> 2, g = tid & 3;
            *(float4*)&xsm[b * 16 + g * 4] =
                *(const float4*)(xkt + (size_t)b * G4H + g * HH + cb);
        }

        unsigned long long acc2[8];   // [p][u]: p batch-pair, u unit
#pragma unroll
        for (int i = 0; i < 8; ++i) acc2[i] = 0ULL;

        const double2* hp = (const double2*)(hcur + ((size_t)s << 12) + (bg << 2));
        const unsigned long long* rp = Rs64 + (cg << 5) + (s << 2);
#pragma unroll 8
        for (int kk = 0; kk < 64; ++kk) {
            double2 hd = __ldcg(hp + kk * 16);  // 64 floats/row -> 16 double2
            unsigned long long h01 = __double_as_longlong(hd.x);
            unsigned long long h23 = __double_as_longlong(hd.y);
            const ulonglong2* rv2 = (const ulonglong2*)(rp + (kk << 7));
            ulonglong2 rA = rv2[0];
            ulonglong2 rB = rv2[1];
            FMA2(acc2[0], h01, rA.x);
            FMA2(acc2[1], h01, rA.y);
            FMA2(acc2[2], h01, rB.x);
            FMA2(acc2[3], h01, rB.y);
            FMA2(acc2[4], h23, rA.x);
            FMA2(acc2[5], h23, rA.y);
            FMA2(acc2[6], h23, rB.x);
            FMA2(acc2[7], h23, rB.y);
        }
        // reduce 8 k-split lanes down to s==0 (packed adds)
#pragma unroll
        for (int i = 0; i < 8; ++i) {
            unsigned long long o;
            o = __shfl_down_sync(0xffffffffu, acc2[i], 4, 8); ADD2(acc2[i], acc2[i], o);
            o = __shfl_down_sync(0xffffffffu, acc2[i], 2, 8); ADD2(acc2[i], acc2[i], o);
            o = __shfl_down_sync(0xffffffffu, acc2[i], 1, 8); ADD2(acc2[i], acc2[i], o);
        }
        __syncthreads();   // xsm ready; prior-step gsm reads long done
        if (s == 0) {
#pragma unroll
            for (int p = 0; p < 2; ++p)
#pragma unroll
                for (int u = 0; u < 4; ++u) {
                    int b0 = bg * 4 + 2 * p;
                    int jl = cg * 4 + u;
                    unsigned long long v = acc2[p * 4 + u];
                    gsm[b0 * 16 + jl]       = f2lo(v) + xsm[b0 * 16 + jl];
                    gsm[(b0 + 1) * 16 + jl] = f2hi(v) + xsm[(b0 + 1) * 16 + jl];
                }
        }
        __syncthreads();
        if (tid < 256) {
            int b = tid >> 2, u = tid & 3;
            float iv = gsm[b * 16 + u];
            float fv = gsm[b * 16 + 4 + u];
            float gv = gsm[b * 16 + 8 + u];
            float ov = gsm[b * 16 + 12 + u];
            float c = sigf(fv) * csm[tid] + sigf(iv) * tanhf(gv);
            float h = sigf(ov) * tanhf(c);
            csm[tid] = c;
            __stcg(&hnxt[(cb + u) * BB + b], h);
            hseq[((size_t)t * BB + b) * HH + cb + u] = h;
        }
        grid_barrier();   // h[t] visible to all blocks before next step
    }
}

// ------------------------------ LayerNorm ------------------------------------
__global__ __launch_bounds__(128)
void ln_kernel(const float* __restrict__ x, const float* __restrict__ gamma,
               const float* __restrict__ beta, float* __restrict__ y) {
    const int m = blockIdx.x;
    const int tid = threadIdx.x;
    __shared__ float red[4];
    float4 v = *(const float4*)(x + (size_t)m * HH + tid * 4);

    float s = v.x + v.y + v.z + v.w;
#pragma unroll
    for (int o = 16; o; o >>= 1) s += __shfl_down_sync(0xffffffffu, s, o);
    if ((tid & 31) == 0) red[tid >> 5] = s;
    __syncthreads();
    float mu = (red[0] + red[1] + red[2] + red[3]) * (1.f / HH);
    __syncthreads();

    float dx = v.x - mu, dy = v.y - mu, dz = v.z - mu, dw = v.w - mu;
    float s2 = dx * dx + dy * dy + dz * dz + dw * dw;
#pragma unroll
    for (int o = 16; o; o >>= 1) s2 += __shfl_down_sync(0xffffffffu, s2, o);
    if ((tid & 31) == 0) red[tid >> 5] = s2;
    __syncthreads();
    float var = (red[0] + red[1] + red[2] + red[3]) * (1.f / HH);
    float rs = rsqrtf(var + 1e-3f);

    float4 g = *(const float4*)(gamma + tid * 4);
    float4 b = *(const float4*)(beta + tid * 4);
    float4 o4;
    o4.x = dx * rs * g.x + b.x;
    o4.y = dy * rs * g.y + b.y;
    o4.z = dz * rs * g.z + b.z;
    o4.w = dw * rs * g.w + b.w;
    *(float4*)(y + (size_t)m * HH + tid * 4) = o4;
}

// ------------------------------ launch ---------------------------------------
extern "C" void kernel_launch(void* const* d_in, const int* in_sizes, int n_in,
                              void* d_out, int out_size) {
    const float* z     = (const float*)d_in[0];
    const float* Wp    = (const float*)d_in[1];
    const float* bp    = (const float*)d_in[2];
    const float* Ws    = (const float*)d_in[3];
    const float* bs    = (const float*)d_in[4];
    const float* K0    = (const float*)d_in[5];
    const float* R0    = (const float*)d_in[6];
    const float* b0    = (const float*)d_in[7];
    const float* K1    = (const float*)d_in[8];
    const float* R1    = (const float*)d_in[9];
    const float* b1    = (const float*)d_in[10];
    const float* K2    = (const float*)d_in[11];
    const float* R2    = (const float*)d_in[12];
    const float* b2    = (const float*)d_in[13];
    const float* gamma = (const float*)d_in[14];
    const float* beta  = (const float*)d_in[15];
    const float* W1    = (const float*)d_in[16];
    const float* b1d   = (const float*)d_in[17];
    const float* W2    = (const float*)d_in[18];
    const float* b2d   = (const float*)d_in[19];
    float* out = (float*)d_out;

    float *xk, *seqA, *seqB, *res, *W0eff, *b0eff;
    cudaGetSymbolAddress((void**)&xk,    d_xk);
    cudaGetSymbolAddress((void**)&seqA,  d_seqA);
    cudaGetSymbolAddress((void**)&seqB,  d_seqB);
    cudaGetSymbolAddress((void**)&res,   d_res);
    cudaGetSymbolAddress((void**)&W0eff, d_W0eff);
    cudaGetSymbolAddress((void**)&b0eff, d_b0eff);

    // 1) fold: b0eff = bp@K0 + b0 ; W0eff = Wp@K0
    bias_fold_kernel<<<G4H / 32, 256>>>(bp, K0, b0);
    sgemm64<0,0,0><<<dim3(G4H/64, ZZ/64), 256>>>(Wp, K0, nullptr,
                                                 W0eff, ZZ, G4H, 2*HH);
    // 2) xK0 = z @ W0eff + b0eff   ([t][b] row order)
    sgemm128<1,0,0,1><<<dim3(G4H/128, MROWS/128), 256>>>(z, nullptr, W0eff, b0eff,
                                                         xk, MROWS, G4H, ZZ);
    // 3) LSTM 0 -> seqA
    lstm_kernel<<<LSTM_BLOCKS, 512>>>(xk, R0, seqA);
    // 4) residual = z @ Ws + bs   ([t][b] row order)
    sgemm128<1,0,0,1><<<dim3(HH/128, MROWS/128), 256>>>(z, nullptr, Ws, bs,
                                                        res, MROWS, HH, ZZ);
    // 5) xK1 = seqA @ K1 + b1
    sgemm128<0,0,0,1><<<dim3(G4H/128, MROWS/128), 256>>>(seqA, nullptr, K1, b1,
                                                         xk, MROWS, G4H, HH);
    // 6) LSTM 1 -> seqB
    lstm_kernel<<<LSTM_BLOCKS, 512>>>(xk, R1, seqB);
    // 7) xK2 = (seqB + res) @ K2 + b2
    sgemm128<0,0,1,1><<<dim3(G4H/128, MROWS/128), 256>>>(seqB, res, K2, b2,
                                                         xk, MROWS, G4H, HH);
    // 8) LSTM 2 -> seqA
    lstm_kernel<<<LSTM_BLOCKS, 512>>>(xk, R2, seqA);
    // 9) LayerNorm: seqA -> seqB
    ln_kernel<<<MROWS, 128>>>(seqA, gamma, beta, seqB);
    // 10) y1 = relu(seqB @ W1 + b1d) -> seqA
    sgemm128<0,1,0,1><<<dim3(HH/128, MROWS/128), 256>>>(seqB, nullptr, W1, b1d,
                                                        seqA, MROWS, HH, HH);
    // 11) out = tanh(seqA @ W2 + b2d) -> d_out  ([b][t] row order)
    sgemm64<2,1,1><<<dim3(FF/64, MROWS/64), 256>>>(seqA, W2, b2d,
                                                   out, MROWS, FF, HH);
}

// round 5
// speedup vs baseline: 4.1010x; 4.1010x over previous
#include <cuda_runtime.h>
#include <math.h>

// Problem dims
#define BB 64
#define TT 256
#define ZZ 128
#define HH 512
#define FF 64
#define MROWS (BB*TT)      // 16384
#define G4H   (4*HH)       // 2048
#define LSTM_BLOCKS (HH/4) // 128

// ------------------------------ scratch buffers ------------------------------
__device__ float d_xk[MROWS * G4H];     // 134 MB  gate pre-activations
__device__ float d_seqA[MROWS * HH];
__device__ float d_seqB[MROWS * HH];
__device__ float d_res[MROWS * HH];
__device__ float d_W0eff[ZZ * G4H];
__device__ float d_b0eff[G4H];
__device__ float d_hT[2 * HH * BB];     // double-buffered h, [buf][hidden][batch]
__device__ unsigned g_arrive;
__device__ unsigned g_gen;

__device__ __forceinline__ float sigf(float x) { return 1.f / (1.f + expf(-x)); }

// packed f32x2 helpers
#define FMA2(c, a, b) \
    asm("fma.rn.f32x2 %0, %2, %3, %1;" : "=l"(c) : "l"(c), "l"(a), "l"(b))
#define ADD2PK(d, a, b) \
    asm("add.rn.f32x2 %0, %1, %2;" : "=l"(d) : "l"(a), "l"(b))

__device__ __forceinline__ float f2lo(unsigned long long v) {
    return __uint_as_float((unsigned)v);
}
__device__ __forceinline__ float f2hi(unsigned long long v) {
    return __uint_as_float((unsigned)(v >> 32));
}

// ------------------------------ grid barrier ---------------------------------
__device__ __forceinline__ void grid_barrier() {
    __syncthreads();
    if (threadIdx.x == 0) {
        __threadfence();
        unsigned my = *(volatile unsigned*)&g_gen;
        if (atomicAdd(&g_arrive, 1u) == gridDim.x - 1u) {
            g_arrive = 0u;
            __threadfence();
            atomicAdd(&g_gen, 1u);
        } else {
            while (*(volatile unsigned*)&g_gen == my) {}
        }
        __threadfence();
    }
    __syncthreads();
}

// ------------------------------ bias fold: b0eff = bp@K0 + b0 ----------------
__global__ void bias_fold_kernel(const float* __restrict__ bp,
                                 const float* __restrict__ K0,
                                 const float* __restrict__ b0) {
    __shared__ float red[8][32];
    const int c = threadIdx.x & 31, s = threadIdx.x >> 5;
    const int j = blockIdx.x * 32 + c;
    float acc = 0.f;
    for (int k = s * 128; k < s * 128 + 128; ++k)
        acc += bp[k] * K0[(size_t)k * G4H + j];
    red[s][c] = acc;
    __syncthreads();
    if (s == 0) {
        float t = 0.f;
#pragma unroll
        for (int r = 0; r < 8; ++r) t += red[r][c];
        d_b0eff[j] = t + b0[j];
    }
}

// ------------------------------ SGEMM 128x128x16, 8x8/thread, scalar FFMA ----
// AMAP: 0 identity row, 1 (m=(t,b) -> source row b*T+t)
// ACT : 0 none, 1 relu
// ADD2A: A := A + A2 (identity-mapped rows)
// HASB: add bias[n]
template<int AMAP, int ACT, int ADD2A, int HASB>
__global__ __launch_bounds__(256, 2)
void sgemm128(const float* __restrict__ A, const float* __restrict__ A2,
              const float* __restrict__ Bm, const float* __restrict__ bias,
              float* __restrict__ C, int M, int N, int K) {
    __shared__ float As[16][128];
    __shared__ float Bs[16][128];
    const int tid = threadIdx.x;
    const int n0 = blockIdx.x * 128, m0 = blockIdx.y * 128;
    const int r = tid >> 2, kq = (tid & 3) * 4;
    const int kb = tid >> 5, n4 = (tid & 31) * 4;
    const int tm = tid >> 4, tn = tid & 15;

    float acc[8][8];
#pragma unroll
    for (int i = 0; i < 8; ++i)
#pragma unroll
        for (int j = 0; j < 8; ++j) acc[i][j] = 0.f;

    for (int k0 = 0; k0 < K; k0 += 16) {
#pragma unroll
        for (int h = 0; h < 2; ++h) {   // A tile, transposed store
            int rr = r + h * 64;
            int m = m0 + rr;
            int arow = (AMAP == 1) ? ((m & 63) * TT + (m >> 6)) : m;
            float4 av = *(const float4*)(A + (size_t)arow * K + k0 + kq);
            if (ADD2A) {
                float4 a2 = *(const float4*)(A2 + (size_t)m * K + k0 + kq);
                av.x += a2.x; av.y += a2.y; av.z += a2.z; av.w += a2.w;
            }
            As[kq + 0][rr] = av.x;
            As[kq + 1][rr] = av.y;
            As[kq + 2][rr] = av.z;
            As[kq + 3][rr] = av.w;
        }
#pragma unroll
        for (int h = 0; h < 2; ++h) {   // B tile
            int kk = kb + h * 8;
            *(float4*)&Bs[kk][n4] =
                *(const float4*)(Bm + (size_t)(k0 + kk) * N + n0 + n4);
        }
        __syncthreads();
#pragma unroll
        for (int k = 0; k < 16; ++k) {
            float4 a0 = *(const float4*)&As[k][tm * 8];
            float4 a1 = *(const float4*)&As[k][tm * 8 + 4];
            float4 b0 = *(const float4*)&Bs[k][tn * 8];
            float4 b1 = *(const float4*)&Bs[k][tn * 8 + 4];
            float ar[8] = {a0.x, a0.y, a0.z, a0.w, a1.x, a1.y, a1.z, a1.w};
            float br[8] = {b0.x, b0.y, b0.z, b0.w, b1.x, b1.y, b1.z, b1.w};
#pragma unroll
            for (int i = 0; i < 8; ++i)
#pragma unroll
                for (int j = 0; j < 8; ++j) acc[i][j] += ar[i] * br[j];
        }
        __syncthreads();
    }

#pragma unroll
    for (int i = 0; i < 8; ++i) {
        int m = m0 + tm * 8 + i;
        size_t ro = (size_t)m * N;
        float vals[8];
#pragma unroll
        for (int j = 0; j < 8; ++j) {
            int n = n0 + tn * 8 + j;
            float t = acc[i][j];
            if (HASB) t += bias[n];
            if (ACT == 1) t = fmaxf(t, 0.f);
            vals[j] = t;
        }
        *(float4*)(C + ro + n0 + tn * 8)     = make_float4(vals[0], vals[1], vals[2], vals[3]);
        *(float4*)(C + ro + n0 + tn * 8 + 4) = make_float4(vals[4], vals[5], vals[6], vals[7]);
    }
}

// ------------------------------ SGEMM 64x64x16 (small shapes) ----------------
// OMAP: 0 identity, 1 (t,b)->(b,t) output rows ; ACT: 0 none, 2 tanh
template<int ACT, int OMAP, int HASB>
__global__ __launch_bounds__(256)
void sgemm64(const float* __restrict__ A, const float* __restrict__ Bm,
             const float* __restrict__ bias, float* __restrict__ C,
             int M, int N, int K) {
    __shared__ float As[16][64];
    __shared__ float Bs[16][64];
    const int tid = threadIdx.x;
    const int tx = tid & 15, ty = tid >> 4;
    const int n0 = blockIdx.x * 64, m0 = blockIdx.y * 64;

    float acc[4][4];
#pragma unroll
    for (int i = 0; i < 4; ++i)
#pragma unroll
        for (int j = 0; j < 4; ++j) acc[i][j] = 0.f;

    const int arowl = tid >> 2;
    const int kq = (tid & 3) * 4;
    const int krow = tid >> 4;
    const int nq = (tid & 15) * 4;

    for (int k0 = 0; k0 < K; k0 += 16) {
        {
            int m = m0 + arowl;
            float4 av = *(const float4*)(A + (size_t)m * K + k0 + kq);
            As[kq + 0][arowl] = av.x;
            As[kq + 1][arowl] = av.y;
            As[kq + 2][arowl] = av.z;
            As[kq + 3][arowl] = av.w;
        }
        *(float4*)&Bs[krow][nq] =
            *(const float4*)(Bm + (size_t)(k0 + krow) * N + n0 + nq);
        __syncthreads();
#pragma unroll
        for (int k = 0; k < 16; ++k) {
            float4 a = *(const float4*)&As[k][ty * 4];
            float4 b = *(const float4*)&Bs[k][tx * 4];
            float ar[4] = {a.x, a.y, a.z, a.w};
            float br[4] = {b.x, b.y, b.z, b.w};
#pragma unroll
            for (int i = 0; i < 4; ++i)
#pragma unroll
                for (int j = 0; j < 4; ++j) acc[i][j] += ar[i] * br[j];
        }
        __syncthreads();
    }

#pragma unroll
    for (int i = 0; i < 4; ++i) {
        int m = m0 + ty * 4 + i;
        size_t ro = (OMAP == 1) ? (size_t)((m & 63) * TT + (m >> 6)) * N
                                : (size_t)m * N;
        float4 v;
        float* vp = (float*)&v;
#pragma unroll
        for (int j = 0; j < 4; ++j) {
            int n = n0 + tx * 4 + j;
            float t = acc[i][j];
            if (HASB) t += bias[n];
            if (ACT == 2) t = tanhf(t);
            vp[j] = t;
        }
        *(float4*)(C + ro + n0 + tx * 4) = v;
    }
}

// ------------------------------ LSTM recurrence v3 ---------------------------
// 128 blocks x 512 threads. Block owns 4 units (16 gate cols j = cg*4+u).
// Per step:
//   1. stage full h (512x64 = 128KB) into SMEM, linear/coalesced copy
//   2. warp w handles k-range [32w, 32w+32); lane = (jg in 2, bg in 16):
//      lane tile = 8 cols x 4 batches; h LDS.128 (consecutive, no dup read),
//      R-dup broadcast LDS.128 x4, 16 FMA2 per k.
//   3. per-warp partials -> SMEM (aliased on hs), reduce across 16 warps,
//      add xk, gate nonlinearity, store h (L2) + hseq.
#define LSTM_SMEM_FLOATS (32768 + 16384 + 1024 + 256)
__global__ __launch_bounds__(512)
void lstm_kernel(const float* __restrict__ xk, const float* __restrict__ R,
                 float* __restrict__ hseq) {
    extern __shared__ float smem[];
    float* hs   = smem;                  // 32768 floats (aliased as pw later)
    float* Rdup = smem + 32768;          // 16384 floats
    float* gsmT = smem + 32768 + 16384;  // 1024 floats [j][b]
    float* csm  = gsmT + 1024;           // 256 floats

    const int tid = threadIdx.x;
    const int cb = blockIdx.x * 4;

    // load R slice duplicated: Rdup[k*32 + j*2 (+1)] = R[k][ (j>>2)*HH + cb + (j&3) ]
    for (int idx = tid; idx < HH * 16; idx += 512) {
        int k = idx >> 4, j = idx & 15;
        float v = R[(size_t)k * G4H + (j >> 2) * HH + cb + (j & 3)];
        Rdup[k * 32 + j * 2]     = v;
        Rdup[k * 32 + j * 2 + 1] = v;
    }
    // zero our 4 rows of h buffer 0 + cell state
    if (tid < 256)
        __stcg(&d_hT[(cb + (tid >> 6)) * BB + (tid & 63)], 0.f);
    if (tid < 256) csm[tid] = 0.f;
    grid_barrier();

    const int lane = tid & 31;
    const int wi   = tid >> 5;       // warp: k-range [32wi, 32wi+32)
    const int jg   = lane >> 4;      // col group (8 cols each)
    const int bg   = lane & 15;      // batch quad

    const ulonglong2* RdU2 = (const ulonglong2*)Rdup;
    const ulonglong2* hsU2 = (const ulonglong2*)hs;

    for (int t = 0; t < TT; ++t) {
        const float* hcur = d_hT + (t & 1) * (HH * BB);
        float* hnxt       = d_hT + ((t + 1) & 1) * (HH * BB);
        const float* xkt  = xk + (size_t)t * BB * G4H;

        // ---- stage h into SMEM (coalesced linear copy, 128KB) ----
        {
            const float4* src = (const float4*)hcur;
            float4* dst = (float4*)hs;
#pragma unroll 8
            for (int i = 0; i < 16; ++i)
                dst[tid + i * 512] = __ldcg(src + tid + i * 512);
        }
        __syncthreads();

        // ---- compute: partial gates over warp's k-range ----
        unsigned long long acc2[8][2];
#pragma unroll
        for (int i = 0; i < 8; ++i) { acc2[i][0] = 0ULL; acc2[i][1] = 0ULL; }

#pragma unroll 4
        for (int kk = 0; kk < 32; ++kk) {
            int k = wi * 32 + kk;
            ulonglong2 h2 = hsU2[k * 16 + bg];            // 4 batches, 2 pairs
            const ulonglong2* rr = RdU2 + k * 8 + jg * 4; // 8 dup'd cols
#pragma unroll
            for (int i = 0; i < 4; ++i) {
                ulonglong2 rv = rr[i];
                FMA2(acc2[2 * i][0],     rv.x, h2.x);
                FMA2(acc2[2 * i][1],     rv.x, h2.y);
                FMA2(acc2[2 * i + 1][0], rv.y, h2.x);
                FMA2(acc2[2 * i + 1][1], rv.y, h2.y);
            }
        }
        __syncthreads();   // everyone done reading hs before aliasing as pw

        // ---- write partials: pw float4 idx = wi*256 + j*16 + bg ----
        {
            float4* pw4 = (float4*)hs;
#pragma unroll
            for (int ji = 0; ji < 8; ++ji) {
                int j = jg * 8 + ji;
                float4 v;
                v.x = f2lo(acc2[ji][0]); v.y = f2hi(acc2[ji][0]);
                v.z = f2lo(acc2[ji][1]); v.w = f2hi(acc2[ji][1]);
                pw4[wi * 256 + j * 16 + bg] = v;
            }
        }
        __syncthreads();

        // ---- reduce across 16 warps + xk add -> gsmT[j][b] ----
        {
            int j  = tid >> 5;       // 0..15
            int bp = tid & 31;       // batch pair 0..31
            const unsigned long long* pw2 = (const unsigned long long*)hs;
            unsigned long long a = pw2[j * 32 + bp];
#pragma unroll
            for (int w2 = 1; w2 < 16; ++w2) {
                unsigned long long o = pw2[w2 * 512 + j * 32 + bp];
                ADD2PK(a, a, o);
            }
            int b0 = bp * 2;
            int col = (j >> 2) * HH + cb + (j & 3);
            float g0 = f2lo(a) + __ldg(xkt + (size_t)b0 * G4H + col);
            float g1 = f2hi(a) + __ldg(xkt + (size_t)(b0 + 1) * G4H + col);
            ((float2*)gsmT)[j * 32 + bp] = make_float2(g0, g1);
        }
        __syncthreads();

        // ---- gate nonlinearity, state update, stores ----
        if (tid < 256) {
            int b = tid >> 2, u = tid & 3;
            float iv = gsmT[u * BB + b];
            float fv = gsmT[(4 + u) * BB + b];
            float gv = gsmT[(8 + u) * BB + b];
            float ov = gsmT[(12 + u) * BB + b];
            float c = sigf(fv) * csm[tid] + sigf(iv) * tanhf(gv);
            float h = sigf(ov) * tanhf(c);
            csm[tid] = c;
            __stcg(&hnxt[(cb + u) * BB + b], h);
            hseq[((size_t)t * BB + b) * HH + cb + u] = h;
        }
        grid_barrier();   // h[t] visible to all blocks before next step
    }
}

// ------------------------------ LayerNorm ------------------------------------
__global__ __launch_bounds__(128)
void ln_kernel(const float* __restrict__ x, const float* __restrict__ gamma,
               const float* __restrict__ beta, float* __restrict__ y) {
    const int m = blockIdx.x;
    const int tid = threadIdx.x;
    __shared__ float red[4];
    float4 v = *(const float4*)(x + (size_t)m * HH + tid * 4);

    float s = v.x + v.y + v.z + v.w;
#pragma unroll
    for (int o = 16; o; o >>= 1) s += __shfl_down_sync(0xffffffffu, s, o);
    if ((tid & 31) == 0) red[tid >> 5] = s;
    __syncthreads();
    float mu = (red[0] + red[1] + red[2] + red[3]) * (1.f / HH);
    __syncthreads();

    float dx = v.x - mu, dy = v.y - mu, dz = v.z - mu, dw = v.w - mu;
    float s2 = dx * dx + dy * dy + dz * dz + dw * dw;
#pragma unroll
    for (int o = 16; o; o >>= 1) s2 += __shfl_down_sync(0xffffffffu, s2, o);
    if ((tid & 31) == 0) red[tid >> 5] = s2;
    __syncthreads();
    float var = (red[0] + red[1] + red[2] + red[3]) * (1.f / HH);
    float rs = rsqrtf(var + 1e-3f);

    float4 g = *(const float4*)(gamma + tid * 4);
    float4 b = *(const float4*)(beta + tid * 4);
    float4 o4;
    o4.x = dx * rs * g.x + b.x;
    o4.y = dy * rs * g.y + b.y;
    o4.z = dz * rs * g.z + b.z;
    o4.w = dw * rs * g.w + b.w;
    *(float4*)(y + (size_t)m * HH + tid * 4) = o4;
}

// ------------------------------ launch ---------------------------------------
extern "C" void kernel_launch(void* const* d_in, const int* in_sizes, int n_in,
                              void* d_out, int out_size) {
    const float* z     = (const float*)d_in[0];
    const float* Wp    = (const float*)d_in[1];
    const float* bp    = (const float*)d_in[2];
    const float* Ws    = (const float*)d_in[3];
    const float* bs    = (const float*)d_in[4];
    const float* K0    = (const float*)d_in[5];
    const float* R0    = (const float*)d_in[6];
    const float* b0    = (const float*)d_in[7];
    const float* K1    = (const float*)d_in[8];
    const float* R1    = (const float*)d_in[9];
    const float* b1    = (const float*)d_in[10];
    const float* K2    = (const float*)d_in[11];
    const float* R2    = (const float*)d_in[12];
    const float* b2    = (const float*)d_in[13];
    const float* gamma = (const float*)d_in[14];
    const float* beta  = (const float*)d_in[15];
    const float* W1    = (const float*)d_in[16];
    const float* b1d   = (const float*)d_in[17];
    const float* W2    = (const float*)d_in[18];
    const float* b2d   = (const float*)d_in[19];
    float* out = (float*)d_out;

    float *xk, *seqA, *seqB, *res, *W0eff, *b0eff;
    cudaGetSymbolAddress((void**)&xk,    d_xk);
    cudaGetSymbolAddress((void**)&seqA,  d_seqA);
    cudaGetSymbolAddress((void**)&seqB,  d_seqB);
    cudaGetSymbolAddress((void**)&res,   d_res);
    cudaGetSymbolAddress((void**)&W0eff, d_W0eff);
    cudaGetSymbolAddress((void**)&b0eff, d_b0eff);

    // idempotent, called every launch (no static guards allowed)
    const int lstm_smem = LSTM_SMEM_FLOATS * 4;  // ~197 KB
    cudaFuncSetAttribute(lstm_kernel,
                         cudaFuncAttributeMaxDynamicSharedMemorySize,
                         lstm_smem);

    // 1) fold: b0eff = bp@K0 + b0 ; W0eff = Wp@K0
    bias_fold_kernel<<<G4H / 32, 256>>>(bp, K0, b0);
    sgemm64<0,0,0><<<dim3(G4H/64, ZZ/64), 256>>>(Wp, K0, nullptr,
                                                 W0eff, ZZ, G4H, 2*HH);
    // 2) xK0 = z @ W0eff + b0eff   ([t][b] row order)
    sgemm128<1,0,0,1><<<dim3(G4H/128, MROWS/128), 256>>>(z, nullptr, W0eff, b0eff,
                                                         xk, MROWS, G4H, ZZ);
    // 3) LSTM 0 -> seqA
    lstm_kernel<<<LSTM_BLOCKS, 512, lstm_smem>>>(xk, R0, seqA);
    // 4) residual = z @ Ws + bs   ([t][b] row order)
    sgemm128<1,0,0,1><<<dim3(HH/128, MROWS/128), 256>>>(z, nullptr, Ws, bs,
                                                        res, MROWS, HH, ZZ);
    // 5) xK1 = seqA @ K1 + b1
    sgemm128<0,0,0,1><<<dim3(G4H/128, MROWS/128), 256>>>(seqA, nullptr, K1, b1,
                                                         xk, MROWS, G4H, HH);
    // 6) LSTM 1 -> seqB
    lstm_kernel<<<LSTM_BLOCKS, 512, lstm_smem>>>(xk, R1, seqB);
    // 7) xK2 = (seqB + res) @ K2 + b2
    sgemm128<0,0,1,1><<<dim3(G4H/128, MROWS/128), 256>>>(seqB, res, K2, b2,
                                                         xk, MROWS, G4H, HH);
    // 8) LSTM 2 -> seqA
    lstm_kernel<<<LSTM_BLOCKS, 512, lstm_smem>>>(xk, R2, seqA);
    // 9) LayerNorm: seqA -> seqB
    ln_kernel<<<MROWS, 128>>>(seqA, gamma, beta, seqB);
    // 10) y1 = relu(seqB @ W1 + b1d) -> seqA
    sgemm128<0,1,0,1><<<dim3(HH/128, MROWS/128), 256>>>(seqB, nullptr, W1, b1d,
                                                        seqA, MROWS, HH, HH);
    // 11) out = tanh(seqA @ W2 + b2d) -> d_out  ([b][t] row order)
    sgemm64<2,1,1><<<dim3(FF/64, MROWS/64), 256>>>(seqA, W2, b2d,
                                                   out, MROWS, FF, HH);
}

// round 6
// speedup vs baseline: 4.2902x; 1.0461x over previous
#include <cuda_runtime.h>
#include <math.h>

// Problem dims
#define BB 64
#define TT 256
#define ZZ 128
#define HH 512
#define FF 64
#define MROWS (BB*TT)      // 16384
#define G4H   (4*HH)       // 2048
#define LSTM_BLOCKS (HH/4) // 128

// ------------------------------ scratch buffers ------------------------------
__device__ float d_xk[MROWS * G4H];     // 134 MB  gate pre-activations
__device__ float d_seqA[MROWS * HH];
__device__ float d_seqB[MROWS * HH];
__device__ float d_res[MROWS * HH];
__device__ float d_W0eff[ZZ * G4H];
__device__ float d_b0eff[G4H];
__device__ float d_hT[2 * HH * BB];     // double-buffered h, [buf][hidden][batch]
__device__ unsigned g_grp[8];           // hierarchical barrier: 8 groups of 16
__device__ unsigned g_root;
__device__ unsigned g_gen;

__device__ __forceinline__ float sigf(float x) { return 1.f / (1.f + expf(-x)); }

// packed f32x2 helpers
#define FMA2(c, a, b) \
    asm("fma.rn.f32x2 %0, %2, %3, %1;" : "=l"(c) : "l"(c), "l"(a), "l"(b))
#define ADD2PK(d, a, b) \
    asm("add.rn.f32x2 %0, %1, %2;" : "=l"(d) : "l"(a), "l"(b))

__device__ __forceinline__ float f2lo(unsigned long long v) {
    return __uint_as_float((unsigned)v);
}
__device__ __forceinline__ float f2hi(unsigned long long v) {
    return __uint_as_float((unsigned)(v >> 32));
}

// ------------------------------ hierarchical grid barrier --------------------
// 2-level arrival (16-way group -> 8-way root) to avoid 128-way serialized
// RMW on one L2 line. Counters are monotonic (mod arithmetic), no reset race.
__device__ __forceinline__ void grid_barrier(int grp) {
    __syncthreads();
    if (threadIdx.x == 0) {
        __threadfence();
        unsigned my = *(volatile unsigned*)&g_gen;
        if ((atomicAdd(&g_grp[grp], 1u) & 15u) == 15u) {
            if ((atomicAdd(&g_root, 1u) & 7u) == 7u) {
                atomicAdd(&g_gen, 1u);
            }
        }
        while (*(volatile unsigned*)&g_gen == my) {}
        __threadfence();
    }
    __syncthreads();
}

// ------------------------------ bias fold: b0eff = bp@K0 + b0 ----------------
__global__ void bias_fold_kernel(const float* __restrict__ bp,
                                 const float* __restrict__ K0,
                                 const float* __restrict__ b0) {
    __shared__ float red[8][32];
    const int c = threadIdx.x & 31, s = threadIdx.x >> 5;
    const int j = blockIdx.x * 32 + c;
    float acc = 0.f;
    for (int k = s * 128; k < s * 128 + 128; ++k)
        acc += bp[k] * K0[(size_t)k * G4H + j];
    red[s][c] = acc;
    __syncthreads();
    if (s == 0) {
        float t = 0.f;
#pragma unroll
        for (int r = 0; r < 8; ++r) t += red[r][c];
        d_b0eff[j] = t + b0[j];
    }
}

// ------------------------------ SGEMM 128x128x16, 8x8/thread, scalar FFMA ----
// AMAP: 0 identity row, 1 (m=(t,b) -> source row b*T+t)
// ACT : 0 none, 1 relu
// ADD2A: A := A + A2 (identity-mapped rows)
// HASB: add bias[n]
template<int AMAP, int ACT, int ADD2A, int HASB>
__global__ __launch_bounds__(256, 2)
void sgemm128(const float* __restrict__ A, const float* __restrict__ A2,
              const float* __restrict__ Bm, const float* __restrict__ bias,
              float* __restrict__ C, int M, int N, int K) {
    __shared__ float As[16][128];
    __shared__ float Bs[16][128];
    const int tid = threadIdx.x;
    const int n0 = blockIdx.x * 128, m0 = blockIdx.y * 128;
    const int r = tid >> 2, kq = (tid & 3) * 4;
    const int kb = tid >> 5, n4 = (tid & 31) * 4;
    const int tm = tid >> 4, tn = tid & 15;

    float acc[8][8];
#pragma unroll
    for (int i = 0; i < 8; ++i)
#pragma unroll
        for (int j = 0; j < 8; ++j) acc[i][j] = 0.f;

    for (int k0 = 0; k0 < K; k0 += 16) {
#pragma unroll
        for (int h = 0; h < 2; ++h) {   // A tile, transposed store
            int rr = r + h * 64;
            int m = m0 + rr;
            int arow = (AMAP == 1) ? ((m & 63) * TT + (m >> 6)) : m;
            float4 av = *(const float4*)(A + (size_t)arow * K + k0 + kq);
            if (ADD2A) {
                float4 a2 = *(const float4*)(A2 + (size_t)m * K + k0 + kq);
                av.x += a2.x; av.y += a2.y; av.z += a2.z; av.w += a2.w;
            }
            As[kq + 0][rr] = av.x;
            As[kq + 1][rr] = av.y;
            As[kq + 2][rr] = av.z;
            As[kq + 3][rr] = av.w;
        }
#pragma unroll
        for (int h = 0; h < 2; ++h) {   // B tile
            int kk = kb + h * 8;
            *(float4*)&Bs[kk][n4] =
                *(const float4*)(Bm + (size_t)(k0 + kk) * N + n0 + n4);
        }
        __syncthreads();
#pragma unroll
        for (int k = 0; k < 16; ++k) {
            float4 a0 = *(const float4*)&As[k][tm * 8];
            float4 a1 = *(const float4*)&As[k][tm * 8 + 4];
            float4 b0 = *(const float4*)&Bs[k][tn * 8];
            float4 b1 = *(const float4*)&Bs[k][tn * 8 + 4];
            float ar[8] = {a0.x, a0.y, a0.z, a0.w, a1.x, a1.y, a1.z, a1.w};
            float br[8] = {b0.x, b0.y, b0.z, b0.w, b1.x, b1.y, b1.z, b1.w};
#pragma unroll
            for (int i = 0; i < 8; ++i)
#pragma unroll
                for (int j = 0; j < 8; ++j) acc[i][j] += ar[i] * br[j];
        }
        __syncthreads();
    }

#pragma unroll
    for (int i = 0; i < 8; ++i) {
        int m = m0 + tm * 8 + i;
        size_t ro = (size_t)m * N;
        float vals[8];
#pragma unroll
        for (int j = 0; j < 8; ++j) {
            int n = n0 + tn * 8 + j;
            float t = acc[i][j];
            if (HASB) t += bias[n];
            if (ACT == 1) t = fmaxf(t, 0.f);
            vals[j] = t;
        }
        *(float4*)(C + ro + n0 + tn * 8)     = make_float4(vals[0], vals[1], vals[2], vals[3]);
        *(float4*)(C + ro + n0 + tn * 8 + 4) = make_float4(vals[4], vals[5], vals[6], vals[7]);
    }
}

// ------------------------------ SGEMM 64x64x16 (small shapes) ----------------
// OMAP: 0 identity, 1 (t,b)->(b,t) output rows ; ACT: 0 none, 2 tanh
template<int ACT, int OMAP, int HASB>
__global__ __launch_bounds__(256)
void sgemm64(const float* __restrict__ A, const float* __restrict__ Bm,
             const float* __restrict__ bias, float* __restrict__ C,
             int M, int N, int K) {
    __shared__ float As[16][64];
    __shared__ float Bs[16][64];
    const int tid = threadIdx.x;
    const int tx = tid & 15, ty = tid >> 4;
    const int n0 = blockIdx.x * 64, m0 = blockIdx.y * 64;

    float acc[4][4];
#pragma unroll
    for (int i = 0; i < 4; ++i)
#pragma unroll
        for (int j = 0; j < 4; ++j) acc[i][j] = 0.f;

    const int arowl = tid >> 2;
    const int kq = (tid & 3) * 4;
    const int krow = tid >> 4;
    const int nq = (tid & 15) * 4;

    for (int k0 = 0; k0 < K; k0 += 16) {
        {
            int m = m0 + arowl;
            float4 av = *(const float4*)(A + (size_t)m * K + k0 + kq);
            As[kq + 0][arowl] = av.x;
            As[kq + 1][arowl] = av.y;
            As[kq + 2][arowl] = av.z;
            As[kq + 3][arowl] = av.w;
        }
        *(float4*)&Bs[krow][nq] =
            *(const float4*)(Bm + (size_t)(k0 + krow) * N + n0 + nq);
        __syncthreads();
#pragma unroll
        for (int k = 0; k < 16; ++k) {
            float4 a = *(const float4*)&As[k][ty * 4];
            float4 b = *(const float4*)&Bs[k][tx * 4];
            float ar[4] = {a.x, a.y, a.z, a.w};
            float br[4] = {b.x, b.y, b.z, b.w};
#pragma unroll
            for (int i = 0; i < 4; ++i)
#pragma unroll
                for (int j = 0; j < 4; ++j) acc[i][j] += ar[i] * br[j];
        }
        __syncthreads();
    }

#pragma unroll
    for (int i = 0; i < 4; ++i) {
        int m = m0 + ty * 4 + i;
        size_t ro = (OMAP == 1) ? (size_t)((m & 63) * TT + (m >> 6)) * N
                                : (size_t)m * N;
        float4 v;
        float* vp = (float*)&v;
#pragma unroll
        for (int j = 0; j < 4; ++j) {
            int n = n0 + tx * 4 + j;
            float t = acc[i][j];
            if (HASB) t += bias[n];
            if (ACT == 2) t = tanhf(t);
            vp[j] = t;
        }
        *(float4*)(C + ro + n0 + tx * 4) = v;
    }
}

// ------------------------------ LSTM recurrence v4 ---------------------------
// 128 blocks x 512 threads. Block owns 4 units (16 gate cols j).
// Changes vs v3: h read directly from L2 inside the FMA loop (no SMEM staging,
// no staging sync), xk prefetched into registers before compute, hierarchical
// grid barrier. Per step: 2 __syncthreads + grid barrier.
#define LSTM_SMEM_FLOATS (16384 + 16384 + 1024 + 256)
__global__ __launch_bounds__(512)
void lstm_kernel(const float* __restrict__ xk, const float* __restrict__ R,
                 float* __restrict__ hseq) {
    extern __shared__ float smem[];
    float* pw   = smem;                  // 16384 floats: per-warp partials
    float* Rdup = smem + 16384;          // 16384 floats: duplicated R slice
    float* gsmT = smem + 32768;          // 1024 floats [j][b]
    float* csm  = gsmT + 1024;           // 256 floats

    const int tid = threadIdx.x;
    const int cb  = blockIdx.x * 4;
    const int grp = blockIdx.x >> 4;

    // load R slice duplicated: Rdup[k*32 + j*2 (+1)] = R[k][ (j>>2)*HH + cb + (j&3) ]
    for (int idx = tid; idx < HH * 16; idx += 512) {
        int k = idx >> 4, j = idx & 15;
        float v = R[(size_t)k * G4H + (j >> 2) * HH + cb + (j & 3)];
        Rdup[k * 32 + j * 2]     = v;
        Rdup[k * 32 + j * 2 + 1] = v;
    }
    // zero our 4 rows of h buffer 0 + cell state
    if (tid < 256)
        __stcg(&d_hT[(cb + (tid >> 6)) * BB + (tid & 63)], 0.f);
    if (tid < 256) csm[tid] = 0.f;
    grid_barrier(grp);

    const int lane = tid & 31;
    const int wi   = tid >> 5;       // warp: k-range [32wi, 32wi+32)
    const int jg   = lane >> 4;      // col group (8 cols each)
    const int bg   = lane & 15;      // batch quad

    const ulonglong2* RdU2 = (const ulonglong2*)Rdup;

    // reduce-phase fixed indices
    const int rj   = tid >> 5;       // gate col 0..15
    const int rbp  = tid & 31;       // batch pair 0..31
    const int rb0  = rbp * 2;
    const int rcol = (rj >> 2) * HH + cb + (rj & 3);

    for (int t = 0; t < TT; ++t) {
        const float* hcur = d_hT + (t & 1) * (HH * BB);
        float* hnxt       = d_hT + ((t + 1) & 1) * (HH * BB);
        const float* xkt  = xk + (size_t)t * BB * G4H;

        // prefetch xk values for the reduce phase (latency hidden by compute)
        float xpre0 = __ldg(xkt + (size_t)rb0 * G4H + rcol);
        float xpre1 = __ldg(xkt + (size_t)(rb0 + 1) * G4H + rcol);

        // ---- compute: partial gates over warp's k-range, h straight from L2 --
        unsigned long long acc2[8][2];
#pragma unroll
        for (int i = 0; i < 8; ++i) { acc2[i][0] = 0ULL; acc2[i][1] = 0ULL; }

        const double2* hp = (const double2*)(hcur + wi * 32 * 64 + bg * 4);
        const ulonglong2* rp = RdU2 + wi * 32 * 8 + jg * 4;
#pragma unroll 8
        for (int kk = 0; kk < 32; ++kk) {
            double2 hd = __ldcg(hp + kk * 16);   // 64 floats/row -> 16 double2
            unsigned long long h01 = __double_as_longlong(hd.x);
            unsigned long long h23 = __double_as_longlong(hd.y);
            const ulonglong2* rr = rp + kk * 8;
#pragma unroll
            for (int i = 0; i < 4; ++i) {
                ulonglong2 rv = rr[i];
                FMA2(acc2[2 * i][0],     rv.x, h01);
                FMA2(acc2[2 * i][1],     rv.x, h23);
                FMA2(acc2[2 * i + 1][0], rv.y, h01);
                FMA2(acc2[2 * i + 1][1], rv.y, h23);
            }
        }

        // ---- write partials: pw float4 idx = wi*256 + j*16 + bg ----
        {
            float4* pw4 = (float4*)pw;
#pragma unroll
            for (int ji = 0; ji < 8; ++ji) {
                int j = jg * 8 + ji;
                float4 v;
                v.x = f2lo(acc2[ji][0]); v.y = f2hi(acc2[ji][0]);
                v.z = f2lo(acc2[ji][1]); v.w = f2hi(acc2[ji][1]);
                pw4[wi * 256 + j * 16 + bg] = v;
            }
        }
        __syncthreads();

        // ---- reduce across 16 warps + xk add -> gsmT[j][b] ----
        {
            const unsigned long long* pw2 = (const unsigned long long*)pw;
            unsigned long long a = pw2[rj * 32 + rbp];
#pragma unroll
            for (int w2 = 1; w2 < 16; ++w2) {
                unsigned long long o = pw2[w2 * 512 + rj * 32 + rbp];
                ADD2PK(a, a, o);
            }
            float g0 = f2lo(a) + xpre0;
            float g1 = f2hi(a) + xpre1;
            ((float2*)gsmT)[rj * 32 + rbp] = make_float2(g0, g1);
        }
        __syncthreads();

        // ---- gate nonlinearity, state update, stores ----
        if (tid < 256) {
            int b = tid >> 2, u = tid & 3;
            float iv = gsmT[u * BB + b];
            float fv = gsmT[(4 + u) * BB + b];
            float gv = gsmT[(8 + u) * BB + b];
            float ov = gsmT[(12 + u) * BB + b];
            float c = sigf(fv) * csm[tid] + sigf(iv) * tanhf(gv);
            float h = sigf(ov) * tanhf(c);
            csm[tid] = c;
            __stcg(&hnxt[(cb + u) * BB + b], h);
            hseq[((size_t)t * BB + b) * HH + cb + u] = h;
        }
        grid_barrier(grp);   // h[t] visible to all blocks before next step
    }
}

// ------------------------------ LayerNorm ------------------------------------
__global__ __launch_bounds__(128)
void ln_kernel(const float* __restrict__ x, const float* __restrict__ gamma,
               const float* __restrict__ beta, float* __restrict__ y) {
    const int m = blockIdx.x;
    const int tid = threadIdx.x;
    __shared__ float red[4];
    float4 v = *(const float4*)(x + (size_t)m * HH + tid * 4);

    float s = v.x + v.y + v.z + v.w;
#pragma unroll
    for (int o = 16; o; o >>= 1) s += __shfl_down_sync(0xffffffffu, s, o);
    if ((tid & 31) == 0) red[tid >> 5] = s;
    __syncthreads();
    float mu = (red[0] + red[1] + red[2] + red[3]) * (1.f / HH);
    __syncthreads();

    float dx = v.x - mu, dy = v.y - mu, dz = v.z - mu, dw = v.w - mu;
    float s2 = dx * dx + dy * dy + dz * dz + dw * dw;
#pragma unroll
    for (int o = 16; o; o >>= 1) s2 += __shfl_down_sync(0xffffffffu, s2, o);
    if ((tid & 31) == 0) red[tid >> 5] = s2;
    __syncthreads();
    float var = (red[0] + red[1] + red[2] + red[3]) * (1.f / HH);
    float rs = rsqrtf(var + 1e-3f);

    float4 g = *(const float4*)(gamma + tid * 4);
    float4 b = *(const float4*)(beta + tid * 4);
    float4 o4;
    o4.x = dx * rs * g.x + b.x;
    o4.y = dy * rs * g.y + b.y;
    o4.z = dz * rs * g.z + b.z;
    o4.w = dw * rs * g.w + b.w;
    *(float4*)(y + (size_t)m * HH + tid * 4) = o4;
}

// ------------------------------ launch ---------------------------------------
extern "C" void kernel_launch(void* const* d_in, const int* in_sizes, int n_in,
                              void* d_out, int out_size) {
    const float* z     = (const float*)d_in[0];
    const float* Wp    = (const float*)d_in[1];
    const float* bp    = (const float*)d_in[2];
    const float* Ws    = (const float*)d_in[3];
    const float* bs    = (const float*)d_in[4];
    const float* K0    = (const float*)d_in[5];
    const float* R0    = (const float*)d_in[6];
    const float* b0    = (const float*)d_in[7];
    const float* K1    = (const float*)d_in[8];
    const float* R1    = (const float*)d_in[9];
    const float* b1    = (const float*)d_in[10];
    const float* K2    = (const float*)d_in[11];
    const float* R2    = (const float*)d_in[12];
    const float* b2    = (const float*)d_in[13];
    const float* gamma = (const float*)d_in[14];
    const float* beta  = (const float*)d_in[15];
    const float* W1    = (const float*)d_in[16];
    const float* b1d   = (const float*)d_in[17];
    const float* W2    = (const float*)d_in[18];
    const float* b2d   = (const float*)d_in[19];
    float* out = (float*)d_out;

    float *xk, *seqA, *seqB, *res, *W0eff, *b0eff;
    cudaGetSymbolAddress((void**)&xk,    d_xk);
    cudaGetSymbolAddress((void**)&seqA,  d_seqA);
    cudaGetSymbolAddress((void**)&seqB,  d_seqB);
    cudaGetSymbolAddress((void**)&res,   d_res);
    cudaGetSymbolAddress((void**)&W0eff, d_W0eff);
    cudaGetSymbolAddress((void**)&b0eff, d_b0eff);

    // idempotent, called every launch (no static guards allowed)
    const int lstm_smem = LSTM_SMEM_FLOATS * 4;  // ~134 KB
    cudaFuncSetAttribute(lstm_kernel,
                         cudaFuncAttributeMaxDynamicSharedMemorySize,
                         lstm_smem);

    // 1) fold: b0eff = bp@K0 + b0 ; W0eff = Wp@K0
    bias_fold_kernel<<<G4H / 32, 256>>>(bp, K0, b0);
    sgemm64<0,0,0><<<dim3(G4H/64, ZZ/64), 256>>>(Wp, K0, nullptr,
                                                 W0eff, ZZ, G4H, 2*HH);
    // 2) xK0 = z @ W0eff + b0eff   ([t][b] row order)
    sgemm128<1,0,0,1><<<dim3(G4H/128, MROWS/128), 256>>>(z, nullptr, W0eff, b0eff,
                                                         xk, MROWS, G4H, ZZ);
    // 3) LSTM 0 -> seqA
    lstm_kernel<<<LSTM_BLOCKS, 512, lstm_smem>>>(xk, R0, seqA);
    // 4) residual = z @ Ws + bs   ([t][b] row order)
    sgemm128<1,0,0,1><<<dim3(HH/128, MROWS/128), 256>>>(z, nullptr, Ws, bs,
                                                        res, MROWS, HH, ZZ);
    // 5) xK1 = seqA @ K1 + b1
    sgemm128<0,0,0,1><<<dim3(G4H/128, MROWS/128), 256>>>(seqA, nullptr, K1, b1,
                                                         xk, MROWS, G4H, HH);
    // 6) LSTM 1 -> seqB
    lstm_kernel<<<LSTM_BLOCKS, 512, lstm_smem>>>(xk, R1, seqB);
    // 7) xK2 = (seqB + res) @ K2 + b2
    sgemm128<0,0,1,1><<<dim3(G4H/128, MROWS/128), 256>>>(seqB, res, K2, b2,
                                                         xk, MROWS, G4H, HH);
    // 8) LSTM 2 -> seqA
    lstm_kernel<<<LSTM_BLOCKS, 512, lstm_smem>>>(xk, R2, seqA);
    // 9) LayerNorm: seqA -> seqB
    ln_kernel<<<MROWS, 128>>>(seqA, gamma, beta, seqB);
    // 10) y1 = relu(seqB @ W1 + b1d) -> seqA
    sgemm128<0,1,0,1><<<dim3(HH/128, MROWS/128), 256>>>(seqB, nullptr, W1, b1d,
                                                        seqA, MROWS, HH, HH);
    // 11) out = tanh(seqA @ W2 + b2d) -> d_out  ([b][t] row order)
    sgemm64<2,1,1><<<dim3(FF/64, MROWS/64), 256>>>(seqA, W2, b2d,
                                                   out, MROWS, FF, HH);
}